// round 15
// baseline (speedup 1.0000x reference)
#include <cuda_runtime.h>
#include <cuda_bf16.h>
#include <cstdint>

// VectorQuantizer via mma.sync (HMMA) bf16 3-split GEMM + cp.async pipeline.
// R14: 4 accumulator chains (dep distance 4) to cover HMMA latency.
// z: 65536 x 64 fp32, codebook: 1024 x 64 fp32.
// argmin_v (|c_v|^2 - 2 z.c_v)   [ |z|^2 row-constant, dropped ]
// out: [z_q 65536*64 | tokens 65536 (float) | codebook 1024*64]

#define NROWS   65536
#define DDIM    64
#define VOCAB   1024
#define THREADS 256          // 8 warps; CTA covers 128 rows (16 rows/warp)
#define M_CTA   128
#define N_CHUNK 64           // codes per pipeline stage
#define NCHUNKS (VOCAB / N_CHUNK)   // 16

// smem: two B buffers (3 splits x 64 codes x 144B) + c2[1024]
#define ROWPITCH 144
#define BUFSZ    (3 * N_CHUNK * ROWPITCH)   // 27648
#define SMEM_C2  (2 * BUFSZ)                // 55296
#define SMEM_TOTAL (SMEM_C2 + VOCAB * 4)    // 59392

__device__ __nv_bfloat16 d_cb_split[3][VOCAB][DDIM];
__device__ float d_c2[VOCAB];

__device__ __forceinline__ void split3(float x, unsigned short h[3]) {
    __nv_bfloat16 b1 = __float2bfloat16(x);
    float r1 = x - __bfloat162float(b1);
    __nv_bfloat16 b2 = __float2bfloat16(r1);
    float r2 = r1 - __bfloat162float(b2);
    __nv_bfloat16 b3 = __float2bfloat16(r2);
    h[0] = __bfloat16_as_ushort(b1);
    h[1] = __bfloat16_as_ushort(b2);
    h[2] = __bfloat16_as_ushort(b3);
}

// m16n8k16 row.col f32.bf16.bf16.f32 — PTX ISA baseline (sm_80+)
#define MMA16816(Cp, A0, A1, A2, A3, B0, B1)                                  \
    asm volatile(                                                             \
        "mma.sync.aligned.m16n8k16.row.col.f32.bf16.bf16.f32 "                \
        "{%0,%1,%2,%3}, {%4,%5,%6,%7}, {%8,%9}, {%0,%1,%2,%3};"               \
        : "+f"((Cp)[0]), "+f"((Cp)[1]), "+f"((Cp)[2]), "+f"((Cp)[3])          \
        : "r"(A0), "r"(A1), "r"(A2), "r"(A3), "r"(B0), "r"(B1))

#define CP_ASYNC16(dst_u32, src_ptr)                                          \
    asm volatile("cp.async.cg.shared.global [%0], [%1], 16;"                  \
                 :: "r"(dst_u32), "l"(src_ptr))
#define CP_COMMIT()  asm volatile("cp.async.commit_group;" ::: "memory")
#define CP_WAIT(n)   asm volatile("cp.async.wait_group %0;" :: "n"(n) : "memory")

__device__ __forceinline__ unsigned smem_u32(const void* p) {
    unsigned a;
    asm("{ .reg .u64 t; cvta.to.shared.u64 t, %1; cvt.u32.u64 %0, t; }" : "=r"(a) : "l"(p));
    return a;
}

// ---------------- prep: warp per code, lane = 2 columns ----------------------
__global__ void vq_prep_kernel(const float* __restrict__ cb) {
    const int gw   = (blockIdx.x * blockDim.x + threadIdx.x) >> 5;  // code id
    const int lane = threadIdx.x & 31;
    if (gw >= VOCAB) return;
    float2 v = *reinterpret_cast<const float2*>(cb + (size_t)gw * DDIM + lane * 2);
    unsigned short hx[3], hy[3];
    split3(v.x, hx); split3(v.y, hy);
#pragma unroll
    for (int s = 0; s < 3; s++) {
        ushort2 p; p.x = hx[s]; p.y = hy[s];
        *reinterpret_cast<ushort2*>(&d_cb_split[s][gw][lane * 2]) = p;
    }
    float ss = v.x * v.x + v.y * v.y;
#pragma unroll
    for (int off = 16; off >= 1; off >>= 1)
        ss += __shfl_xor_sync(0xFFFFFFFFu, ss, off);
    if (lane == 0) d_c2[gw] = ss;
}

// ---------------- main HMMA kernel with cp.async double buffer ---------------
__global__ void __launch_bounds__(THREADS, 2)
vq_mma_kernel(const float* __restrict__ z, const float* __restrict__ cb,
              float* __restrict__ out_q, float* __restrict__ out_tok) {
    extern __shared__ char smem[];
    float* s_c2 = reinterpret_cast<float*>(smem + SMEM_C2);
    const unsigned sbase = smem_u32(smem);

    const int tid  = threadIdx.x;
    const int w    = tid >> 5;
    const int lane = tid & 31;
    const int qrow = lane >> 2;   // 0..7
    const int qcol = lane & 3;    // 0..3

    const int rowLo = blockIdx.x * M_CTA + w * 16 + qrow;
    const int rowHi = rowLo + 8;

    // stage c2 (whole vocab, 4KB)
    for (int i = tid; i < VOCAB; i += THREADS) s_c2[i] = d_c2[i];

    // Build A fragments: 3 splits x 4 ktiles x 4 regs, straight from gmem z.
    unsigned A[3][4][4];
#pragma unroll
    for (int t = 0; t < 4; t++) {
        const int c = t * 16 + qcol * 2;
        float2 v00 = *reinterpret_cast<const float2*>(z + (size_t)rowLo * DDIM + c);
        float2 v10 = *reinterpret_cast<const float2*>(z + (size_t)rowHi * DDIM + c);
        float2 v01 = *reinterpret_cast<const float2*>(z + (size_t)rowLo * DDIM + c + 8);
        float2 v11 = *reinterpret_cast<const float2*>(z + (size_t)rowHi * DDIM + c + 8);
        unsigned short hx[3], hy[3];
        split3(v00.x, hx); split3(v00.y, hy);
#pragma unroll
        for (int s = 0; s < 3; s++) A[s][t][0] = (unsigned)hx[s] | ((unsigned)hy[s] << 16);
        split3(v10.x, hx); split3(v10.y, hy);
#pragma unroll
        for (int s = 0; s < 3; s++) A[s][t][1] = (unsigned)hx[s] | ((unsigned)hy[s] << 16);
        split3(v01.x, hx); split3(v01.y, hy);
#pragma unroll
        for (int s = 0; s < 3; s++) A[s][t][2] = (unsigned)hx[s] | ((unsigned)hy[s] << 16);
        split3(v11.x, hx); split3(v11.y, hy);
#pragma unroll
        for (int s = 0; s < 3; s++) A[s][t][3] = (unsigned)hx[s] | ((unsigned)hy[s] << 16);
    }

    float bLo = 3.402823466e+38f, bHi = 3.402823466e+38f;
    int   iLo = 0, iHi = 0;

    // stage chunk -> buffer via cp.async (6 x 16B per thread)
    auto stage = [&](int chunk, int buf) {
        const int base = chunk * N_CHUNK;
        const unsigned dst0 = sbase + buf * BUFSZ;
        for (int i = tid; i < 3 * N_CHUNK * 8; i += THREADS) {
            int s = i >> 9, rem = i & 511, code = rem >> 3, c16 = rem & 7;
            const void* src = &d_cb_split[s][base + code][c16 * 8];
            CP_ASYNC16(dst0 + (s * N_CHUNK + code) * ROWPITCH + c16 * 16, src);
        }
    };

    stage(0, 0);
    CP_COMMIT();

    for (int chunk = 0; chunk < NCHUNKS; chunk++) {
        __syncthreads();  // WAR: buffer (chunk+1)&1 fully consumed (chunk-1 compute)
        if (chunk + 1 < NCHUNKS) {
            stage(chunk + 1, (chunk + 1) & 1);
            CP_COMMIT();
            CP_WAIT(1);   // chunk's group done; chunk+1 may be in flight
        } else {
            CP_WAIT(0);
        }
        __syncthreads();

        const char* smemB = smem + (chunk & 1) * BUFSZ;
        const int base = chunk * N_CHUNK;

#pragma unroll 1
        for (int n8 = 0; n8 < N_CHUNK / 8; n8++) {
            const int codeB = n8 * 8 + qrow;
            unsigned Bf[3][4][2];
#pragma unroll
            for (int s = 0; s < 3; s++) {
                const char* rowp = smemB + (s * N_CHUNK + codeB) * ROWPITCH + qcol * 4;
#pragma unroll
                for (int t = 0; t < 4; t++) {
                    Bf[s][t][0] = *reinterpret_cast<const unsigned*>(rowp + t * 32);
                    Bf[s][t][1] = *reinterpret_cast<const unsigned*>(rowp + t * 32 + 16);
                }
            }

            // 4 accumulator chains, round-robin: consecutive MMAs -> different
            // accumulators (dep distance 4); 6 MMAs per chain.
            float C[4][4] = {{0.f,0.f,0.f,0.f},{0.f,0.f,0.f,0.f},
                             {0.f,0.f,0.f,0.f},{0.f,0.f,0.f,0.f}};
#pragma unroll
            for (int t = 0; t < 4; t++) {
                MMA16816(C[(6*t+0)&3], A[0][t][0], A[0][t][1], A[0][t][2], A[0][t][3], Bf[0][t][0], Bf[0][t][1]);
                MMA16816(C[(6*t+1)&3], A[0][t][0], A[0][t][1], A[0][t][2], A[0][t][3], Bf[1][t][0], Bf[1][t][1]);
                MMA16816(C[(6*t+2)&3], A[1][t][0], A[1][t][1], A[1][t][2], A[1][t][3], Bf[0][t][0], Bf[0][t][1]);
                MMA16816(C[(6*t+3)&3], A[0][t][0], A[0][t][1], A[0][t][2], A[0][t][3], Bf[2][t][0], Bf[2][t][1]);
                MMA16816(C[(6*t+4)&3], A[2][t][0], A[2][t][1], A[2][t][2], A[2][t][3], Bf[0][t][0], Bf[0][t][1]);
                MMA16816(C[(6*t+5)&3], A[1][t][0], A[1][t][1], A[1][t][2], A[1][t][3], Bf[1][t][0], Bf[1][t][1]);
            }

            const int nc0 = base + n8 * 8 + qcol * 2;
            const int nc1 = nc0 + 1;
            const float c20 = s_c2[nc0], c21 = s_c2[nc1];
            float d00 = c20 - 2.0f * (C[0][0] + C[1][0] + C[2][0] + C[3][0]);
            float d01 = c21 - 2.0f * (C[0][1] + C[1][1] + C[2][1] + C[3][1]);
            float d10 = c20 - 2.0f * (C[0][2] + C[1][2] + C[2][2] + C[3][2]);
            float d11 = c21 - 2.0f * (C[0][3] + C[1][3] + C[2][3] + C[3][3]);
            if (d00 < bLo) { bLo = d00; iLo = nc0; }
            if (d01 < bLo) { bLo = d01; iLo = nc1; }
            if (d10 < bHi) { bHi = d10; iHi = nc0; }
            if (d11 < bHi) { bHi = d11; iHi = nc1; }
        }
    }

    // quad reduction (lanes 4q..4q+3: same rows, disjoint code subsets)
#pragma unroll
    for (int off = 1; off <= 2; off <<= 1) {
        float dl = __shfl_xor_sync(0xFFFFFFFFu, bLo, off);
        int   il = __shfl_xor_sync(0xFFFFFFFFu, iLo, off);
        if (dl < bLo || (dl == bLo && il < iLo)) { bLo = dl; iLo = il; }
        float dh = __shfl_xor_sync(0xFFFFFFFFu, bHi, off);
        int   ih = __shfl_xor_sync(0xFFFFFFFFu, iHi, off);
        if (dh < bHi || (dh == bHi && ih < iHi)) { bHi = dh; iHi = ih; }
    }

    if (qcol == 0) {
        out_tok[rowLo] = (float)iLo;
        out_tok[rowHi] = (float)iHi;
    }
    {
        const float4* sLo = reinterpret_cast<const float4*>(cb + (size_t)iLo * DDIM);
        const float4* sHi = reinterpret_cast<const float4*>(cb + (size_t)iHi * DDIM);
        float4* dLo = reinterpret_cast<float4*>(out_q + (size_t)rowLo * DDIM);
        float4* dHi = reinterpret_cast<float4*>(out_q + (size_t)rowHi * DDIM);
#pragma unroll
        for (int j = 0; j < 4; j++) {
            dLo[qcol + 4 * j] = sLo[qcol + 4 * j];
            dHi[qcol + 4 * j] = sHi[qcol + 4 * j];
        }
    }
}

extern "C" void kernel_launch(void* const* d_in, const int* in_sizes, int n_in,
                              void* d_out, int out_size) {
    const float* z  = (const float*)d_in[0];
    const float* cb = (const float*)d_in[1];
    float* out = (float*)d_out;

    float* out_q   = out;
    float* out_tok = out + (size_t)NROWS * DDIM;
    float* out_cb  = out_tok + NROWS;

    cudaFuncSetAttribute(vq_mma_kernel,
                         cudaFuncAttributeMaxDynamicSharedMemorySize, SMEM_TOTAL);

    vq_prep_kernel<<<(VOCAB * 32) / THREADS, THREADS>>>(cb);
    vq_mma_kernel<<<NROWS / M_CTA, THREADS, SMEM_TOTAL>>>(z, cb, out_q, out_tok);
    cudaMemcpyAsync(out_cb, cb, (size_t)VOCAB * DDIM * sizeof(float),
                    cudaMemcpyDeviceToDevice);
}

// round 16
// speedup vs baseline: 1.0576x; 1.0576x over previous
#include <cuda_runtime.h>
#include <cuda_bf16.h>
#include <cstdint>

// VectorQuantizer via mma.sync (HMMA) bf16 3-split GEMM + cp.async pipeline.
// R16: M-doubling — warp computes two m16 tiles sharing B fragments
//      (HMMA:LDS ratio 2:1) to raise tensor-pipe occupancy.
// z: 65536 x 64 fp32, codebook: 1024 x 64 fp32.
// argmin_v (|c_v|^2 - 2 z.c_v)   [ |z|^2 row-constant, dropped ]
// out: [z_q 65536*64 | tokens 65536 (float) | codebook 1024*64]

#define NROWS   65536
#define DDIM    64
#define VOCAB   1024
#define THREADS 128          // 4 warps; warp covers 32 rows (2 m16 tiles)
#define M_CTA   128
#define N_CHUNK 64           // codes per pipeline stage
#define NCHUNKS (VOCAB / N_CHUNK)   // 16

// smem: two B buffers (3 splits x 64 codes x 144B) + c2[1024]
#define ROWPITCH 144
#define BUFSZ    (3 * N_CHUNK * ROWPITCH)   // 27648
#define SMEM_C2  (2 * BUFSZ)                // 55296
#define SMEM_TOTAL (SMEM_C2 + VOCAB * 4)    // 59392

__device__ __nv_bfloat16 d_cb_split[3][VOCAB][DDIM];
__device__ float d_c2[VOCAB];

__device__ __forceinline__ void split3(float x, unsigned short h[3]) {
    __nv_bfloat16 b1 = __float2bfloat16(x);
    float r1 = x - __bfloat162float(b1);
    __nv_bfloat16 b2 = __float2bfloat16(r1);
    float r2 = r1 - __bfloat162float(b2);
    __nv_bfloat16 b3 = __float2bfloat16(r2);
    h[0] = __bfloat16_as_ushort(b1);
    h[1] = __bfloat16_as_ushort(b2);
    h[2] = __bfloat16_as_ushort(b3);
}

// m16n8k16 row.col f32.bf16.bf16.f32 — PTX ISA baseline (sm_80+)
#define MMA16816(Cp, A0, A1, A2, A3, B0, B1)                                  \
    asm volatile(                                                             \
        "mma.sync.aligned.m16n8k16.row.col.f32.bf16.bf16.f32 "                \
        "{%0,%1,%2,%3}, {%4,%5,%6,%7}, {%8,%9}, {%0,%1,%2,%3};"               \
        : "+f"((Cp)[0]), "+f"((Cp)[1]), "+f"((Cp)[2]), "+f"((Cp)[3])          \
        : "r"(A0), "r"(A1), "r"(A2), "r"(A3), "r"(B0), "r"(B1))

#define CP_ASYNC16(dst_u32, src_ptr)                                          \
    asm volatile("cp.async.cg.shared.global [%0], [%1], 16;"                  \
                 :: "r"(dst_u32), "l"(src_ptr))
#define CP_COMMIT()  asm volatile("cp.async.commit_group;" ::: "memory")
#define CP_WAIT(n)   asm volatile("cp.async.wait_group %0;" :: "n"(n) : "memory")

__device__ __forceinline__ unsigned smem_u32(const void* p) {
    unsigned a;
    asm("{ .reg .u64 t; cvta.to.shared.u64 t, %1; cvt.u32.u64 %0, t; }" : "=r"(a) : "l"(p));
    return a;
}

// ---------------- prep: warp per code, lane = 2 columns ----------------------
__global__ void vq_prep_kernel(const float* __restrict__ cb) {
    const int gw   = (blockIdx.x * blockDim.x + threadIdx.x) >> 5;  // code id
    const int lane = threadIdx.x & 31;
    if (gw >= VOCAB) return;
    float2 v = *reinterpret_cast<const float2*>(cb + (size_t)gw * DDIM + lane * 2);
    unsigned short hx[3], hy[3];
    split3(v.x, hx); split3(v.y, hy);
#pragma unroll
    for (int s = 0; s < 3; s++) {
        ushort2 p; p.x = hx[s]; p.y = hy[s];
        *reinterpret_cast<ushort2*>(&d_cb_split[s][gw][lane * 2]) = p;
    }
    float ss = v.x * v.x + v.y * v.y;
#pragma unroll
    for (int off = 16; off >= 1; off >>= 1)
        ss += __shfl_xor_sync(0xFFFFFFFFu, ss, off);
    if (lane == 0) d_c2[gw] = ss;
}

// ---------------- main HMMA kernel: 2 m16 tiles per warp ---------------------
__global__ void __launch_bounds__(THREADS, 2)
vq_mma_kernel(const float* __restrict__ z, const float* __restrict__ cb,
              float* __restrict__ out_q, float* __restrict__ out_tok) {
    extern __shared__ char smem[];
    float* s_c2 = reinterpret_cast<float*>(smem + SMEM_C2);
    const unsigned sbase = smem_u32(smem);

    const int tid  = threadIdx.x;
    const int w    = tid >> 5;
    const int lane = tid & 31;
    const int qrow = lane >> 2;   // 0..7
    const int qcol = lane & 3;    // 0..3

    // warp owns rows [w*32, w*32+32): tile0 = rows +qrow, +qrow+8
    //                                 tile1 = rows +qrow+16, +qrow+24
    const int r0 = blockIdx.x * M_CTA + w * 32 + qrow;
    const int r1 = r0 + 8;
    const int r2 = r0 + 16;
    const int r3 = r0 + 24;

    // stage c2 (whole vocab, 4KB)
    for (int i = tid; i < VOCAB; i += THREADS) s_c2[i] = d_c2[i];

    // Build A fragments for both tiles: 2 x 3 splits x 4 ktiles x 4 regs.
    unsigned A0[3][4][4], A1[3][4][4];
#pragma unroll
    for (int t = 0; t < 4; t++) {
        const int c = t * 16 + qcol * 2;
        unsigned short hx[3], hy[3];
#pragma unroll
        for (int half = 0; half < 2; half++) {
            const int cc = c + half * 8;   // a0/a1 (k lo) then a2/a3 (k hi)
            float2 v0 = *reinterpret_cast<const float2*>(z + (size_t)r0 * DDIM + cc);
            float2 v1 = *reinterpret_cast<const float2*>(z + (size_t)r1 * DDIM + cc);
            float2 v2 = *reinterpret_cast<const float2*>(z + (size_t)r2 * DDIM + cc);
            float2 v3 = *reinterpret_cast<const float2*>(z + (size_t)r3 * DDIM + cc);
            split3(v0.x, hx); split3(v0.y, hy);
#pragma unroll
            for (int s = 0; s < 3; s++) A0[s][t][2 * half + 0] = (unsigned)hx[s] | ((unsigned)hy[s] << 16);
            split3(v1.x, hx); split3(v1.y, hy);
#pragma unroll
            for (int s = 0; s < 3; s++) A0[s][t][2 * half + 1] = (unsigned)hx[s] | ((unsigned)hy[s] << 16);
            split3(v2.x, hx); split3(v2.y, hy);
#pragma unroll
            for (int s = 0; s < 3; s++) A1[s][t][2 * half + 0] = (unsigned)hx[s] | ((unsigned)hy[s] << 16);
            split3(v3.x, hx); split3(v3.y, hy);
#pragma unroll
            for (int s = 0; s < 3; s++) A1[s][t][2 * half + 1] = (unsigned)hx[s] | ((unsigned)hy[s] << 16);
        }
    }
    // NOTE: A-fragment reg order is {a0,a1,a2,a3} = {(rLo,kLo),(rHi,kLo),(rLo,kHi),(rHi,kHi)}
    // same as previous rounds (half=0 fills a0,a1; half=1 fills a2,a3).

    float b0 = 3.402823466e+38f, b1v = 3.402823466e+38f;
    float b2v = 3.402823466e+38f, b3v = 3.402823466e+38f;
    int   i0 = 0, i1 = 0, i2 = 0, i3 = 0;

    // stage chunk -> buffer via cp.async (12 x 16B per thread)
    auto stage = [&](int chunk, int buf) {
        const int base = chunk * N_CHUNK;
        const unsigned dst0 = sbase + buf * BUFSZ;
        for (int i = tid; i < 3 * N_CHUNK * 8; i += THREADS) {
            int s = i >> 9, rem = i & 511, code = rem >> 3, c16 = rem & 7;
            const void* src = &d_cb_split[s][base + code][c16 * 8];
            CP_ASYNC16(dst0 + (s * N_CHUNK + code) * ROWPITCH + c16 * 16, src);
        }
    };

    stage(0, 0);
    CP_COMMIT();

    for (int chunk = 0; chunk < NCHUNKS; chunk++) {
        __syncthreads();  // WAR: buffer (chunk+1)&1 fully consumed
        if (chunk + 1 < NCHUNKS) {
            stage(chunk + 1, (chunk + 1) & 1);
            CP_COMMIT();
            CP_WAIT(1);
        } else {
            CP_WAIT(0);
        }
        __syncthreads();

        const char* smemB = smem + (chunk & 1) * BUFSZ;
        const int base = chunk * N_CHUNK;

#pragma unroll 1
        for (int n8 = 0; n8 < N_CHUNK / 8; n8++) {
            const int codeB = n8 * 8 + qrow;
            unsigned Bf[3][4][2];
#pragma unroll
            for (int s = 0; s < 3; s++) {
                const char* rowp = smemB + (s * N_CHUNK + codeB) * ROWPITCH + qcol * 4;
#pragma unroll
                for (int t = 0; t < 4; t++) {
                    Bf[s][t][0] = *reinterpret_cast<const unsigned*>(rowp + t * 32);
                    Bf[s][t][1] = *reinterpret_cast<const unsigned*>(rowp + t * 32 + 16);
                }
            }

            // 48 HMMA per n8: 6 split-passes x 4 ktiles x 2 tiles.
            // 2 chains per tile; B fragment reused by both tiles.
            float C0[2][4] = {{0,0,0,0},{0,0,0,0}};
            float C1[2][4] = {{0,0,0,0},{0,0,0,0}};
            const int pi[6] = {0, 0, 1, 0, 2, 1};
            const int pj[6] = {0, 1, 0, 2, 0, 1};
#pragma unroll
            for (int t = 0; t < 4; t++) {
#pragma unroll
                for (int p = 0; p < 6; p++) {
                    const int s = pi[p], q = pj[p], ch = p & 1;
                    MMA16816(C0[ch], A0[s][t][0], A0[s][t][1], A0[s][t][2], A0[s][t][3], Bf[q][t][0], Bf[q][t][1]);
                    MMA16816(C1[ch], A1[s][t][0], A1[s][t][1], A1[s][t][2], A1[s][t][3], Bf[q][t][0], Bf[q][t][1]);
                }
            }

            const int nc0 = base + n8 * 8 + qcol * 2;
            const int nc1 = nc0 + 1;
            const float c20 = s_c2[nc0], c21 = s_c2[nc1];
            float d00 = c20 - 2.0f * (C0[0][0] + C0[1][0]);
            float d01 = c21 - 2.0f * (C0[0][1] + C0[1][1]);
            float d10 = c20 - 2.0f * (C0[0][2] + C0[1][2]);
            float d11 = c21 - 2.0f * (C0[0][3] + C0[1][3]);
            float e00 = c20 - 2.0f * (C1[0][0] + C1[1][0]);
            float e01 = c21 - 2.0f * (C1[0][1] + C1[1][1]);
            float e10 = c20 - 2.0f * (C1[0][2] + C1[1][2]);
            float e11 = c21 - 2.0f * (C1[0][3] + C1[1][3]);
            if (d00 < b0)  { b0 = d00;  i0 = nc0; }
            if (d01 < b0)  { b0 = d01;  i0 = nc1; }
            if (d10 < b1v) { b1v = d10; i1 = nc0; }
            if (d11 < b1v) { b1v = d11; i1 = nc1; }
            if (e00 < b2v) { b2v = e00; i2 = nc0; }
            if (e01 < b2v) { b2v = e01; i2 = nc1; }
            if (e10 < b3v) { b3v = e10; i3 = nc0; }
            if (e11 < b3v) { b3v = e11; i3 = nc1; }
        }
    }

    // quad reduction (lanes 4q..4q+3: same rows, disjoint code subsets)
#pragma unroll
    for (int off = 1; off <= 2; off <<= 1) {
        float t0 = __shfl_xor_sync(0xFFFFFFFFu, b0, off);
        int   j0 = __shfl_xor_sync(0xFFFFFFFFu, i0, off);
        if (t0 < b0 || (t0 == b0 && j0 < i0)) { b0 = t0; i0 = j0; }
        float t1 = __shfl_xor_sync(0xFFFFFFFFu, b1v, off);
        int   j1 = __shfl_xor_sync(0xFFFFFFFFu, i1, off);
        if (t1 < b1v || (t1 == b1v && j1 < i1)) { b1v = t1; i1 = j1; }
        float t2 = __shfl_xor_sync(0xFFFFFFFFu, b2v, off);
        int   j2 = __shfl_xor_sync(0xFFFFFFFFu, i2, off);
        if (t2 < b2v || (t2 == b2v && j2 < i2)) { b2v = t2; i2 = j2; }
        float t3 = __shfl_xor_sync(0xFFFFFFFFu, b3v, off);
        int   j3 = __shfl_xor_sync(0xFFFFFFFFu, i3, off);
        if (t3 < b3v || (t3 == b3v && j3 < i3)) { b3v = t3; i3 = j3; }
    }

    if (qcol == 0) {
        out_tok[r0] = (float)i0;
        out_tok[r1] = (float)i1;
        out_tok[r2] = (float)i2;
        out_tok[r3] = (float)i3;
    }
    {
        const float4* s0 = reinterpret_cast<const float4*>(cb + (size_t)i0 * DDIM);
        const float4* s1 = reinterpret_cast<const float4*>(cb + (size_t)i1 * DDIM);
        const float4* s2 = reinterpret_cast<const float4*>(cb + (size_t)i2 * DDIM);
        const float4* s3 = reinterpret_cast<const float4*>(cb + (size_t)i3 * DDIM);
        float4* o0 = reinterpret_cast<float4*>(out_q + (size_t)r0 * DDIM);
        float4* o1 = reinterpret_cast<float4*>(out_q + (size_t)r1 * DDIM);
        float4* o2 = reinterpret_cast<float4*>(out_q + (size_t)r2 * DDIM);
        float4* o3 = reinterpret_cast<float4*>(out_q + (size_t)r3 * DDIM);
#pragma unroll
        for (int j = 0; j < 4; j++) {
            o0[qcol + 4 * j] = s0[qcol + 4 * j];
            o1[qcol + 4 * j] = s1[qcol + 4 * j];
            o2[qcol + 4 * j] = s2[qcol + 4 * j];
            o3[qcol + 4 * j] = s3[qcol + 4 * j];
        }
    }
}

extern "C" void kernel_launch(void* const* d_in, const int* in_sizes, int n_in,
                              void* d_out, int out_size) {
    const float* z  = (const float*)d_in[0];
    const float* cb = (const float*)d_in[1];
    float* out = (float*)d_out;

    float* out_q   = out;
    float* out_tok = out + (size_t)NROWS * DDIM;
    float* out_cb  = out_tok + NROWS;

    cudaFuncSetAttribute(vq_mma_kernel,
                         cudaFuncAttributeMaxDynamicSharedMemorySize, SMEM_TOTAL);

    vq_prep_kernel<<<(VOCAB * 32) / 256, 256>>>(cb);
    vq_mma_kernel<<<NROWS / M_CTA, THREADS, SMEM_TOTAL>>>(z, cb, out_q, out_tok);
    cudaMemcpyAsync(out_cb, cb, (size_t)VOCAB * DDIM * sizeof(float),
                    cudaMemcpyDeviceToDevice);
}